// round 1
// baseline (speedup 1.0000x reference)
#include <cuda_runtime.h>
#include <cstddef>

// ---------------- problem constants ----------------
#define B_WIN   4096
#define N_TOK   49
#define C_DIM   128
#define NH      4
#define HD      32
#define NWIN    64
#define M_ROWS  (B_WIN * N_TOK)        // 200704
#define SCALE   0.17677669529663687f   // 32^-0.5

// ---------------- scratch (no cudaMalloc allowed) ----------------
__device__ float g_qkv[(size_t)M_ROWS * 384];   // [B*N, 384] = q|k|v
__device__ float g_att[(size_t)M_ROWS * 128];   // [B*N, 128] attention output (head-merged)

// ---------------- tiled fp32 GEMM: out[M,NCOLS] = A[M,128] @ W[128,NCOLS] + bias ----------------
template <int NCOLS>
__global__ __launch_bounds__(256)
void gemm_kernel(const float* __restrict__ A,
                 const float* __restrict__ W,
                 const float* __restrict__ bias,
                 float* __restrict__ out)
{
    __shared__ float As[64][65];   // [k][m], +1 pad
    __shared__ float Bs[64][64];   // [k][n]

    const int tid = threadIdx.x;        // 256 threads
    const int tx  = tid & 15;           // 0..15 (n direction)
    const int ty  = tid >> 4;           // 0..15 (m direction)
    const int m0  = blockIdx.x * 64;
    const int n0  = blockIdx.y * 64;

    float acc[4][4];
    #pragma unroll
    for (int i = 0; i < 4; i++)
        #pragma unroll
        for (int j = 0; j < 4; j++) acc[i][j] = 0.f;

    #pragma unroll
    for (int k0 = 0; k0 < 128; k0 += 64) {
        // load A tile (transposed into As[k][m]); coalesced float4 global reads
        #pragma unroll
        for (int p = 0; p < 4; p++) {
            int m = ty + p * 16;
            float4 v = *(const float4*)&A[(size_t)(m0 + m) * 128 + k0 + tx * 4];
            As[tx * 4 + 0][m] = v.x;
            As[tx * 4 + 1][m] = v.y;
            As[tx * 4 + 2][m] = v.z;
            As[tx * 4 + 3][m] = v.w;
        }
        // load W tile into Bs[k][n]
        #pragma unroll
        for (int p = 0; p < 4; p++) {
            int k = ty + p * 16;
            *(float4*)&Bs[k][tx * 4] =
                *(const float4*)&W[(size_t)(k0 + k) * NCOLS + n0 + tx * 4];
        }
        __syncthreads();

        #pragma unroll
        for (int k = 0; k < 64; k++) {
            float a0 = As[k][ty * 4 + 0];
            float a1 = As[k][ty * 4 + 1];
            float a2 = As[k][ty * 4 + 2];
            float a3 = As[k][ty * 4 + 3];
            float4 bv = *(const float4*)&Bs[k][tx * 4];
            acc[0][0] += a0 * bv.x; acc[0][1] += a0 * bv.y; acc[0][2] += a0 * bv.z; acc[0][3] += a0 * bv.w;
            acc[1][0] += a1 * bv.x; acc[1][1] += a1 * bv.y; acc[1][2] += a1 * bv.z; acc[1][3] += a1 * bv.w;
            acc[2][0] += a2 * bv.x; acc[2][1] += a2 * bv.y; acc[2][2] += a2 * bv.z; acc[2][3] += a2 * bv.w;
            acc[3][0] += a3 * bv.x; acc[3][1] += a3 * bv.y; acc[3][2] += a3 * bv.z; acc[3][3] += a3 * bv.w;
        }
        __syncthreads();
    }

    #pragma unroll
    for (int i = 0; i < 4; i++) {
        int m = m0 + ty * 4 + i;
        #pragma unroll
        for (int j = 0; j < 4; j++) {
            int n = n0 + tx * 4 + j;
            out[(size_t)m * NCOLS + n] = acc[i][j] + bias[n];
        }
    }
}

// ---------------- fused window attention: one block per (window, head) ----------------
__global__ __launch_bounds__(256)
void attn_kernel(const float* __restrict__ mask,
                 const float* __restrict__ bias_table,
                 const int*   __restrict__ rel_index)
{
    const int w = blockIdx.x;   // window 0..4095
    const int h = blockIdx.y;   // head   0..3

    __shared__ float q[N_TOK][HD];        // broadcast reads -> no pad needed
    __shared__ float kk[N_TOK][HD + 1];   // pad to kill 32-way conflict
    __shared__ float vv[N_TOK][HD + 1];
    __shared__ float S[N_TOK][N_TOK + 1];
    __shared__ float bt[169];

    const int tid = threadIdx.x;  // 256

    const float* base = g_qkv + (size_t)w * N_TOK * 384;
    for (int idx = tid; idx < N_TOK * HD; idx += 256) {
        int n = idx / HD, d = idx % HD;
        q[n][d]  = base[n * 384 +       h * HD + d];
        kk[n][d] = base[n * 384 + 128 + h * HD + d];
        vv[n][d] = base[n * 384 + 256 + h * HD + d];
    }
    if (tid < 169) bt[tid] = bias_table[tid];
    __syncthreads();

    // scores + rel-pos bias + mask
    const float* mrow = mask + (size_t)(w & (NWIN - 1)) * N_TOK * N_TOK;
    for (int idx = tid; idx < N_TOK * N_TOK; idx += 256) {
        int i = idx / N_TOK, j = idx % N_TOK;
        float s = 0.f;
        #pragma unroll
        for (int d = 0; d < HD; d++) s += q[i][d] * kk[j][d];
        S[i][j] = s * SCALE + bt[rel_index[idx]] + mrow[idx];
    }
    __syncthreads();

    // softmax: one thread per row (49 rows)
    if (tid < N_TOK) {
        float mx = -1e30f;
        #pragma unroll 7
        for (int j = 0; j < N_TOK; j++) mx = fmaxf(mx, S[tid][j]);
        float sum = 0.f;
        #pragma unroll 7
        for (int j = 0; j < N_TOK; j++) {
            float e = __expf(S[tid][j] - mx);
            S[tid][j] = e;
            sum += e;
        }
        float inv = 1.f / sum;
        #pragma unroll 7
        for (int j = 0; j < N_TOK; j++) S[tid][j] *= inv;
    }
    __syncthreads();

    // O = P @ V, write into [B, N, H*HD] layout
    float* outb = g_att + (size_t)w * N_TOK * C_DIM + h * HD;
    for (int idx = tid; idx < N_TOK * HD; idx += 256) {
        int i = idx / HD, d = idx % HD;
        float o = 0.f;
        #pragma unroll
        for (int j = 0; j < N_TOK; j++) o += S[i][j] * vv[j][d];
        outb[i * C_DIM + d] = o;
    }
}

// ---------------- launch ----------------
extern "C" void kernel_launch(void* const* d_in, const int* in_sizes, int n_in,
                              void* d_out, int out_size)
{
    const float* x          = (const float*)d_in[0];
    const float* mask       = (const float*)d_in[1];
    const float* qkv_w      = (const float*)d_in[2];
    const float* qkv_b      = (const float*)d_in[3];
    const float* proj_w     = (const float*)d_in[4];
    const float* proj_b     = (const float*)d_in[5];
    const float* bias_table = (const float*)d_in[6];
    const int*   rel_index  = (const int*)d_in[7];
    float*       out        = (float*)d_out;

    void* qkv_ptr = nullptr;
    void* att_ptr = nullptr;
    cudaGetSymbolAddress(&qkv_ptr, g_qkv);
    cudaGetSymbolAddress(&att_ptr, g_att);

    // Stage A: qkv = x @ qkv_w + qkv_b   (200704 x 128 x 384)
    gemm_kernel<384><<<dim3(M_ROWS / 64, 384 / 64), 256>>>(
        x, qkv_w, qkv_b, (float*)qkv_ptr);

    // Stage B: windowed attention (scores + bias + mask + softmax + PV)
    attn_kernel<<<dim3(B_WIN, NH), 256>>>(mask, bias_table, rel_index);

    // Stage C: out = att @ proj_w + proj_b   (200704 x 128 x 128)
    gemm_kernel<128><<<dim3(M_ROWS / 64, 128 / 64), 256>>>(
        (const float*)att_ptr, proj_w, proj_b, out);
}

// round 2
// speedup vs baseline: 1.8106x; 1.8106x over previous
#include <cuda_runtime.h>
#include <cstdint>
#include <cstddef>

// ---------------- problem constants ----------------
#define B_WIN   4096
#define N_TOK   49
#define C_DIM   128
#define NH      4
#define HD      32
#define NWIN    64
#define M_ROWS  (B_WIN * N_TOK)        // 200704
#define SCALE   0.17677669529663687f   // 32^-0.5

// ---------------- scratch (no cudaMalloc allowed) ----------------
__device__ float g_qkv[(size_t)M_ROWS * 384];   // [B*N, 384] = q|k|v
__device__ float g_att[(size_t)M_ROWS * 128];   // [B*N, 128] attention output (head-merged)

__device__ __forceinline__ uint32_t f2tf32(float f) {
    uint32_t r;
    asm("cvt.rna.tf32.f32 %0, %1;" : "=r"(r) : "f"(f));
    return r;
}

__device__ __forceinline__ void mma_tf32(float c[4], const uint32_t a[4], const uint32_t b[2]) {
    asm volatile(
        "mma.sync.aligned.m16n8k8.row.col.f32.tf32.tf32.f32 "
        "{%0,%1,%2,%3}, {%4,%5,%6,%7}, {%8,%9}, {%0,%1,%2,%3};"
        : "+f"(c[0]), "+f"(c[1]), "+f"(c[2]), "+f"(c[3])
        : "r"(a[0]), "r"(a[1]), "r"(a[2]), "r"(a[3]), "r"(b[0]), "r"(b[1]));
}

// ---------------- tf32 tensor-core GEMM: out[M,NCOLS] = A[M,128] @ W[128,NCOLS] + bias ----
// Block tile 128(M) x 128(N), K chunks of 32. 8 warps in 2(M) x 4(N); warp tile 64x32.
#define AS_STRIDE 36   // %32 == 4  -> A-frag reads conflict-free
#define BS_STRIDE 136  // %32 == 8  -> B-frag reads conflict-free

template <int NCOLS>
__global__ __launch_bounds__(256)
void gemm_tc_kernel(const float* __restrict__ A,
                    const float* __restrict__ W,
                    const float* __restrict__ bias,
                    float* __restrict__ out)
{
    __shared__ __align__(16) uint32_t As[128 * AS_STRIDE];
    __shared__ __align__(16) uint32_t Bs[32 * BS_STRIDE];

    const int tid  = threadIdx.x;
    const int lane = tid & 31;
    const int warp = tid >> 5;
    const int wm   = warp >> 2;          // 0..1
    const int wn   = warp & 3;           // 0..3
    const int m0   = blockIdx.x * 128;
    const int n0   = blockIdx.y * 128;

    float acc[4][4][4];
    #pragma unroll
    for (int i = 0; i < 4; i++)
        #pragma unroll
        for (int j = 0; j < 4; j++)
            #pragma unroll
            for (int r = 0; r < 4; r++) acc[i][j][r] = 0.f;

    float4 ra[4], rb[4];
    const int ar  = tid >> 3;    // 0..31
    const int ac4 = tid & 7;     // 0..7
    const int br  = tid >> 5;    // 0..7
    const int bc4 = tid & 31;    // 0..31

    // prefetch chunk 0
    #pragma unroll
    for (int p = 0; p < 4; p++)
        ra[p] = *(const float4*)&A[(size_t)(m0 + ar + p * 32) * 128 + ac4 * 4];
    #pragma unroll
    for (int p = 0; p < 4; p++)
        rb[p] = *(const float4*)&W[(size_t)(br + p * 8) * NCOLS + n0 + bc4 * 4];

    #pragma unroll
    for (int ch = 0; ch < 4; ch++) {
        __syncthreads();
        // store prefetched regs -> smem (tf32-converted), 16B stores
        #pragma unroll
        for (int p = 0; p < 4; p++) {
            uint4 u;
            u.x = f2tf32(ra[p].x); u.y = f2tf32(ra[p].y);
            u.z = f2tf32(ra[p].z); u.w = f2tf32(ra[p].w);
            *(uint4*)&As[(ar + p * 32) * AS_STRIDE + ac4 * 4] = u;
        }
        #pragma unroll
        for (int p = 0; p < 4; p++) {
            uint4 u;
            u.x = f2tf32(rb[p].x); u.y = f2tf32(rb[p].y);
            u.z = f2tf32(rb[p].z); u.w = f2tf32(rb[p].w);
            *(uint4*)&Bs[(br + p * 8) * BS_STRIDE + bc4 * 4] = u;
        }
        __syncthreads();

        if (ch < 3) {
            int k0 = (ch + 1) * 32;
            #pragma unroll
            for (int p = 0; p < 4; p++)
                ra[p] = *(const float4*)&A[(size_t)(m0 + ar + p * 32) * 128 + k0 + ac4 * 4];
            #pragma unroll
            for (int p = 0; p < 4; p++)
                rb[p] = *(const float4*)&W[(size_t)(k0 + br + p * 8) * NCOLS + n0 + bc4 * 4];
        }

        // compute on this chunk: 4 k-steps of 8
        #pragma unroll
        for (int kk = 0; kk < 4; kk++) {
            const int k = kk * 8;
            uint32_t af[4][4];
            #pragma unroll
            for (int mt = 0; mt < 4; mt++) {
                int row = wm * 64 + mt * 16 + (lane >> 2);
                int col = k + (lane & 3);
                af[mt][0] = As[row * AS_STRIDE + col];
                af[mt][1] = As[(row + 8) * AS_STRIDE + col];
                af[mt][2] = As[row * AS_STRIDE + col + 4];
                af[mt][3] = As[(row + 8) * AS_STRIDE + col + 4];
            }
            uint32_t bf[4][2];
            #pragma unroll
            for (int nt = 0; nt < 4; nt++) {
                int col = wn * 32 + nt * 8 + (lane >> 2);
                int row = k + (lane & 3);
                bf[nt][0] = Bs[row * BS_STRIDE + col];
                bf[nt][1] = Bs[(row + 4) * BS_STRIDE + col];
            }
            #pragma unroll
            for (int mt = 0; mt < 4; mt++)
                #pragma unroll
                for (int nt = 0; nt < 4; nt++)
                    mma_tf32(acc[mt][nt], af[mt], bf[nt]);
        }
    }

    // epilogue: add bias, write float2 pairs
    #pragma unroll
    for (int mt = 0; mt < 4; mt++) {
        #pragma unroll
        for (int nt = 0; nt < 4; nt++) {
            int m = m0 + wm * 64 + mt * 16 + (lane >> 2);
            int n = n0 + wn * 32 + nt * 8 + (lane & 3) * 2;
            float b0 = bias[n], b1 = bias[n + 1];
            *(float2*)&out[(size_t)m * NCOLS + n] =
                make_float2(acc[mt][nt][0] + b0, acc[mt][nt][1] + b1);
            *(float2*)&out[(size_t)(m + 8) * NCOLS + n] =
                make_float2(acc[mt][nt][2] + b0, acc[mt][nt][3] + b1);
        }
    }
}

// ---------------- fused window attention: one block per (window, head), 128 thr ------
__global__ __launch_bounds__(128)
void attn_kernel(const float* __restrict__ mask,
                 const float* __restrict__ bias_table,
                 const int*   __restrict__ rel_index)
{
    const int w = blockIdx.x;   // window 0..4095
    const int h = blockIdx.y;   // head   0..3

    __shared__ float q[N_TOK][HD];         // q pre-scaled
    __shared__ float kk[N_TOK][HD + 1];
    __shared__ float vv[N_TOK][HD + 1];
    __shared__ float S[N_TOK][53];         // stride 53: max 2-way conflicts in PV
    __shared__ float bt[169];

    const int tid  = threadIdx.x;
    const int lane = tid & 31;
    const int warp = tid >> 5;

    const float* base = g_qkv + (size_t)w * N_TOK * 384;
    for (int idx = tid; idx < N_TOK * HD; idx += 128) {
        int n = idx >> 5, d = idx & 31;
        q[n][d]  = base[n * 384 +       h * HD + d] * SCALE;
        kk[n][d] = base[n * 384 + 128 + h * HD + d];
        vv[n][d] = base[n * 384 + 256 + h * HD + d];
    }
    for (int i = tid; i < 169; i += 128) bt[i] = bias_table[i];
    __syncthreads();

    // ---- scores: 4x4 register tiles over (i,j), 13x13 = 169 tiles ----
    const float* mrow = mask + (size_t)(w & (NWIN - 1)) * N_TOK * N_TOK;
    for (int t = tid; t < 169; t += 128) {
        int i0 = (t / 13) * 4, j0 = (t % 13) * 4;
        float accs[4][4];
        #pragma unroll
        for (int a = 0; a < 4; a++)
            #pragma unroll
            for (int b = 0; b < 4; b++) accs[a][b] = 0.f;
        #pragma unroll
        for (int d = 0; d < HD; d++) {
            float qa[4], kb[4];
            #pragma unroll
            for (int a = 0; a < 4; a++) qa[a] = q[min(i0 + a, N_TOK - 1)][d];
            #pragma unroll
            for (int b = 0; b < 4; b++) kb[b] = kk[min(j0 + b, N_TOK - 1)][d];
            #pragma unroll
            for (int a = 0; a < 4; a++)
                #pragma unroll
                for (int b = 0; b < 4; b++) accs[a][b] += qa[a] * kb[b];
        }
        #pragma unroll
        for (int a = 0; a < 4; a++) {
            int i = i0 + a;
            if (i >= N_TOK) break;
            #pragma unroll
            for (int b = 0; b < 4; b++) {
                int j = j0 + b;
                if (j < N_TOK)
                    S[i][j] = accs[a][b] + bt[rel_index[i * N_TOK + j]] + mrow[i * N_TOK + j];
            }
        }
    }
    __syncthreads();

    // ---- softmax: warp per row, lanes cover j and j+32 ----
    for (int i = warp; i < N_TOK; i += 4) {
        float v1 = S[i][lane];
        float v2 = (lane + 32 < N_TOK) ? S[i][lane + 32] : -1e30f;
        float mx = fmaxf(v1, v2);
        #pragma unroll
        for (int o = 16; o > 0; o >>= 1) mx = fmaxf(mx, __shfl_xor_sync(0xffffffffu, mx, o));
        float e1 = __expf(v1 - mx);
        float e2 = (lane + 32 < N_TOK) ? __expf(v2 - mx) : 0.f;
        float sum = e1 + e2;
        #pragma unroll
        for (int o = 16; o > 0; o >>= 1) sum += __shfl_xor_sync(0xffffffffu, sum, o);
        float inv = 1.f / sum;
        S[i][lane] = e1 * inv;
        if (lane + 32 < N_TOK) S[i][lane + 32] = e2 * inv;
    }
    __syncthreads();

    // ---- O = P @ V: 4x4 register tiles over (i,d), 13x8 = 104 tiles ----
    float* outb = g_att + (size_t)w * N_TOK * C_DIM + h * HD;
    for (int t = tid; t < 104; t += 128) {
        int i0 = (t / 8) * 4, d0 = (t % 8) * 4;
        float acco[4][4];
        #pragma unroll
        for (int a = 0; a < 4; a++)
            #pragma unroll
            for (int b = 0; b < 4; b++) acco[a][b] = 0.f;
        for (int j = 0; j < N_TOK; j++) {
            float pa[4], vb[4];
            #pragma unroll
            for (int a = 0; a < 4; a++) pa[a] = S[min(i0 + a, N_TOK - 1)][j];
            #pragma unroll
            for (int b = 0; b < 4; b++) vb[b] = vv[j][d0 + b];
            #pragma unroll
            for (int a = 0; a < 4; a++)
                #pragma unroll
                for (int b = 0; b < 4; b++) acco[a][b] += pa[a] * vb[b];
        }
        #pragma unroll
        for (int a = 0; a < 4; a++) {
            int i = i0 + a;
            if (i >= N_TOK) break;
            #pragma unroll
            for (int b = 0; b < 4; b++)
                outb[i * C_DIM + d0 + b] = acco[a][b];
        }
    }
}

// ---------------- launch ----------------
extern "C" void kernel_launch(void* const* d_in, const int* in_sizes, int n_in,
                              void* d_out, int out_size)
{
    const float* x          = (const float*)d_in[0];
    const float* mask       = (const float*)d_in[1];
    const float* qkv_w      = (const float*)d_in[2];
    const float* qkv_b      = (const float*)d_in[3];
    const float* proj_w     = (const float*)d_in[4];
    const float* proj_b     = (const float*)d_in[5];
    const float* bias_table = (const float*)d_in[6];
    const int*   rel_index  = (const int*)d_in[7];
    float*       out        = (float*)d_out;

    void* qkv_ptr = nullptr;
    void* att_ptr = nullptr;
    cudaGetSymbolAddress(&qkv_ptr, g_qkv);
    cudaGetSymbolAddress(&att_ptr, g_att);

    // Stage A: qkv = x @ qkv_w + qkv_b   (200704 x 128 x 384) — tf32 tensor cores
    gemm_tc_kernel<384><<<dim3(M_ROWS / 128, 384 / 128), 256>>>(
        x, qkv_w, qkv_b, (float*)qkv_ptr);

    // Stage B: windowed attention (scores + bias + mask + softmax + PV)
    attn_kernel<<<dim3(B_WIN, NH), 128>>>(mask, bias_table, rel_index);

    // Stage C: out = att @ proj_w + proj_b   (200704 x 128 x 128) — tf32 tensor cores
    gemm_tc_kernel<128><<<dim3(M_ROWS / 128, 128 / 128), 256>>>(
        (const float*)att_ptr, proj_w, proj_b, out);
}

// round 3
// speedup vs baseline: 2.7399x; 1.5132x over previous
#include <cuda_runtime.h>
#include <cstdint>
#include <cstddef>

// ---------------- problem constants ----------------
#define B_WIN   4096
#define N_TOK   49
#define C_DIM   128
#define NH      4
#define HD      32
#define NWIN    64
#define M_ROWS  (B_WIN * N_TOK)        // 200704
#define SCALE   0.17677669529663687f   // 32^-0.5

// ---------------- scratch (no cudaMalloc allowed) ----------------
__device__ __align__(16) float g_qkv[(size_t)M_ROWS * 384];  // [B*N, 384] = q|k|v
__device__ __align__(16) float g_att[(size_t)M_ROWS * 128];  // [B*N, 128]
__device__ __align__(16) float g_bm[NWIN * N_TOK * N_TOK];   // bias[rel] + mask, per window-id

// ---------------- helpers ----------------
__device__ __forceinline__ uint32_t f2tf32(float f) {
    uint32_t r;
    asm("cvt.rna.tf32.f32 %0, %1;" : "=r"(r) : "f"(f));
    return r;
}

__device__ __forceinline__ void mma_tf32(float c[4], const uint32_t a[4], const uint32_t b[2]) {
    asm volatile(
        "mma.sync.aligned.m16n8k8.row.col.f32.tf32.tf32.f32 "
        "{%0,%1,%2,%3}, {%4,%5,%6,%7}, {%8,%9}, {%0,%1,%2,%3};"
        : "+f"(c[0]), "+f"(c[1]), "+f"(c[2]), "+f"(c[3])
        : "r"(a[0]), "r"(a[1]), "r"(a[2]), "r"(a[3]), "r"(b[0]), "r"(b[1]));
}

__device__ __forceinline__ void cp_async16(uint32_t smem_dst, const void* gsrc) {
    asm volatile("cp.async.ca.shared.global [%0], [%1], 16;\n" :: "r"(smem_dst), "l"(gsrc));
}
__device__ __forceinline__ void cp_commit() { asm volatile("cp.async.commit_group;\n"); }
template <int N>
__device__ __forceinline__ void cp_wait() { asm volatile("cp.async.wait_group %0;\n" :: "n"(N)); }

// ---------------- pre-kernel: g_bm = bias_table[rel_index] + mask ----------------
__global__ void bm_kernel(const float* __restrict__ mask,
                          const float* __restrict__ bias_table,
                          const int*   __restrict__ rel_index)
{
    int idx = blockIdx.x * 256 + threadIdx.x;
    if (idx >= NWIN * N_TOK * N_TOK) return;
    int r = idx % (N_TOK * N_TOK);
    g_bm[idx] = mask[idx] + bias_table[rel_index[r]];
}

// ---------------- tf32 GEMM, cp.async double-buffered --------------------------------
// out[M,NCOLS] = A[M,128] @ W[128,NCOLS] + bias. Tile 128x128, K chunks of 32.
#define AS_STRIDE 36   // float stride: A-frag LDS conflict-free
#define BS_STRIDE 136  // float stride: B-frag LDS conflict-free
#define AS_WORDS (128 * AS_STRIDE)
#define BS_WORDS (32 * BS_STRIDE)

template <int NCOLS>
__global__ __launch_bounds__(256, 2)
void gemm_tc_kernel(const float* __restrict__ A,
                    const float* __restrict__ W,
                    const float* __restrict__ bias,
                    float* __restrict__ out)
{
    extern __shared__ float smem[];
    float* As = smem;                 // [2][AS_WORDS]
    float* Bs = smem + 2 * AS_WORDS;  // [2][BS_WORDS]

    const int tid  = threadIdx.x;
    const int lane = tid & 31;
    const int warp = tid >> 5;
    const int wm   = warp >> 2;          // 0..1
    const int wn   = warp & 3;           // 0..3
    const int m0   = blockIdx.x * 128;
    const int n0   = blockIdx.y * 128;

    float acc[4][4][4];
    #pragma unroll
    for (int i = 0; i < 4; i++)
        #pragma unroll
        for (int j = 0; j < 4; j++)
            #pragma unroll
            for (int r = 0; r < 4; r++) acc[i][j][r] = 0.f;

    auto stage_load = [&](int st, int k0) {
        // A tile: 128 rows x 32 floats, 8x16B per row -> 1024 segs / 256 thr = 4
        #pragma unroll
        for (int p = 0; p < 4; p++) {
            int idx = tid + p * 256;
            int row = idx >> 3, seg = idx & 7;
            uint32_t dst = (uint32_t)__cvta_generic_to_shared(
                &As[st * AS_WORDS + row * AS_STRIDE + seg * 4]);
            cp_async16(dst, &A[(size_t)(m0 + row) * 128 + k0 + seg * 4]);
        }
        // B tile: 32 rows x 128 floats, 32x16B per row
        #pragma unroll
        for (int p = 0; p < 4; p++) {
            int idx = tid + p * 256;
            int row = idx >> 5, seg = idx & 31;
            uint32_t dst = (uint32_t)__cvta_generic_to_shared(
                &Bs[st * BS_WORDS + row * BS_STRIDE + seg * 4]);
            cp_async16(dst, &W[(size_t)(k0 + row) * NCOLS + n0 + seg * 4]);
        }
        cp_commit();
    };

    stage_load(0, 0);

    #pragma unroll
    for (int ch = 0; ch < 4; ch++) {
        if (ch < 3) stage_load((ch + 1) & 1, (ch + 1) * 32);
        if (ch < 3) cp_wait<1>(); else cp_wait<0>();
        __syncthreads();

        const float* as = &As[(ch & 1) * AS_WORDS];
        const float* bs = &Bs[(ch & 1) * BS_WORDS];

        #pragma unroll
        for (int kk = 0; kk < 4; kk++) {
            const int k = kk * 8;
            uint32_t af[4][4];
            #pragma unroll
            for (int mt = 0; mt < 4; mt++) {
                int row = wm * 64 + mt * 16 + (lane >> 2);
                int col = k + (lane & 3);
                af[mt][0] = f2tf32(as[row * AS_STRIDE + col]);
                af[mt][1] = f2tf32(as[(row + 8) * AS_STRIDE + col]);
                af[mt][2] = f2tf32(as[row * AS_STRIDE + col + 4]);
                af[mt][3] = f2tf32(as[(row + 8) * AS_STRIDE + col + 4]);
            }
            uint32_t bf[4][2];
            #pragma unroll
            for (int nt = 0; nt < 4; nt++) {
                int col = wn * 32 + nt * 8 + (lane >> 2);
                int row = k + (lane & 3);
                bf[nt][0] = f2tf32(bs[row * BS_STRIDE + col]);
                bf[nt][1] = f2tf32(bs[(row + 4) * BS_STRIDE + col]);
            }
            #pragma unroll
            for (int mt = 0; mt < 4; mt++)
                #pragma unroll
                for (int nt = 0; nt < 4; nt++)
                    mma_tf32(acc[mt][nt], af[mt], bf[nt]);
        }
        __syncthreads();   // stage (ch&1) reusable at iteration ch+1's load
    }

    #pragma unroll
    for (int mt = 0; mt < 4; mt++) {
        #pragma unroll
        for (int nt = 0; nt < 4; nt++) {
            int m = m0 + wm * 64 + mt * 16 + (lane >> 2);
            int n = n0 + wn * 32 + nt * 8 + (lane & 3) * 2;
            float b0 = bias[n], b1 = bias[n + 1];
            *(float2*)&out[(size_t)m * NCOLS + n] =
                make_float2(acc[mt][nt][0] + b0, acc[mt][nt][1] + b1);
            *(float2*)&out[(size_t)(m + 8) * NCOLS + n] =
                make_float2(acc[mt][nt][2] + b0, acc[mt][nt][3] + b1);
        }
    }
}

// ---------------- tensor-core window attention -----------------------------------
// One block per (window, head). 4 warps; tokens padded 49->64, score cols 49->56.
#define QS 36   // tf32 stride for Q/K [tok][dim]
#define VS 40   // tf32 stride for V   [tok][dim]
#define SS 60   // stride for S        [i][j]

__global__ __launch_bounds__(128)
void attn_tc_kernel()
{
    const int w = blockIdx.x;
    const int h = blockIdx.y;

    __shared__ uint32_t Qs[64 * QS];
    __shared__ uint32_t Ks[64 * QS];
    __shared__ uint32_t Vs[64 * VS];
    __shared__ uint32_t S [64 * SS];   // raw scores (float bits), later P (tf32 bits)

    const int tid  = threadIdx.x;
    const int lane = tid & 31;
    const int warp = tid >> 5;

    // ---- load q/k/v for this head, convert to tf32, pad rows 49..63 with zeros ----
    const float* base = g_qkv + (size_t)w * N_TOK * 384;
    for (int idx = tid; idx < N_TOK * 8; idx += 128) {
        int n = idx >> 3, c4 = (idx & 7) * 4;
        float4 qv = *(const float4*)&base[n * 384 +       h * HD + c4];
        float4 kv = *(const float4*)&base[n * 384 + 128 + h * HD + c4];
        float4 vv = *(const float4*)&base[n * 384 + 256 + h * HD + c4];
        Qs[n * QS + c4 + 0] = f2tf32(qv.x * SCALE);
        Qs[n * QS + c4 + 1] = f2tf32(qv.y * SCALE);
        Qs[n * QS + c4 + 2] = f2tf32(qv.z * SCALE);
        Qs[n * QS + c4 + 3] = f2tf32(qv.w * SCALE);
        Ks[n * QS + c4 + 0] = f2tf32(kv.x);
        Ks[n * QS + c4 + 1] = f2tf32(kv.y);
        Ks[n * QS + c4 + 2] = f2tf32(kv.z);
        Ks[n * QS + c4 + 3] = f2tf32(kv.w);
        Vs[n * VS + c4 + 0] = f2tf32(vv.x);
        Vs[n * VS + c4 + 1] = f2tf32(vv.y);
        Vs[n * VS + c4 + 2] = f2tf32(vv.z);
        Vs[n * VS + c4 + 3] = f2tf32(vv.w);
    }
    for (int idx = tid; idx < 15 * HD; idx += 128) {
        int n = N_TOK + (idx >> 5), d = idx & 31;
        Qs[n * QS + d] = 0u;
        Ks[n * QS + d] = 0u;
        Vs[n * VS + d] = 0u;
    }
    __syncthreads();

    // ---- scores: S = Q @ K^T + bm ; warp = m-tile (16 rows), 7 n-tiles of 8 ----
    const float* bm = g_bm + (size_t)(w & (NWIN - 1)) * N_TOK * N_TOK;
    {
        const int row = warp * 16 + (lane >> 2);
        uint32_t af[4][4];
        #pragma unroll
        for (int ks = 0; ks < 4; ks++) {
            int col = ks * 8 + (lane & 3);
            af[ks][0] = Qs[row * QS + col];
            af[ks][1] = Qs[(row + 8) * QS + col];
            af[ks][2] = Qs[row * QS + col + 4];
            af[ks][3] = Qs[(row + 8) * QS + col + 4];
        }
        #pragma unroll
        for (int nt = 0; nt < 7; nt++) {
            float c[4] = {0.f, 0.f, 0.f, 0.f};
            #pragma unroll
            for (int ks = 0; ks < 4; ks++) {
                int nc = nt * 8 + (lane >> 2);
                int kr = ks * 8 + (lane & 3);
                uint32_t bf[2] = { Ks[nc * QS + kr], Ks[nc * QS + kr + 4] };
                mma_tf32(c, af[ks], bf);
            }
            const int i = warp * 16 + (lane >> 2);
            const int j = nt * 8 + 2 * (lane & 3);
            #pragma unroll
            for (int half = 0; half < 2; half++) {
                int ii = i + half * 8;
                float v0 = c[half * 2], v1 = c[half * 2 + 1];
                float o0, o1;
                if (ii < N_TOK) {
                    o0 = (j     < N_TOK) ? v0 + bm[ii * N_TOK + j]     : -1e30f;
                    o1 = (j + 1 < N_TOK) ? v1 + bm[ii * N_TOK + j + 1] : -1e30f;
                } else { o0 = 0.f; o1 = 0.f; }
                S[ii * SS + j]     = __float_as_uint(o0);
                S[ii * SS + j + 1] = __float_as_uint(o1);
            }
        }
    }
    __syncthreads();

    // ---- softmax per row (warp per row); writeback as tf32 bits (becomes P) ----
    for (int i = warp; i < N_TOK; i += 4) {
        float v1 = __uint_as_float(S[i * SS + lane]);
        float v2 = (lane < 24) ? __uint_as_float(S[i * SS + 32 + lane]) : -1e30f;
        float mx = fmaxf(v1, v2);
        #pragma unroll
        for (int o = 16; o > 0; o >>= 1) mx = fmaxf(mx, __shfl_xor_sync(0xffffffffu, mx, o));
        float e1 = __expf(v1 - mx);
        float e2 = (lane < 24) ? __expf(v2 - mx) : 0.f;
        float sum = e1 + e2;
        #pragma unroll
        for (int o = 16; o > 0; o >>= 1) sum += __shfl_xor_sync(0xffffffffu, sum, o);
        float inv = 1.f / sum;
        S[i * SS + lane] = f2tf32(e1 * inv);
        if (lane < 24) S[i * SS + 32 + lane] = f2tf32(e2 * inv);
    }
    __syncthreads();

    // ---- O = P @ V ; warp = m-tile, 4 n-tiles (dims), 7 k-steps ----
    {
        const int row = warp * 16 + (lane >> 2);
        uint32_t af[7][4];
        #pragma unroll
        for (int ks = 0; ks < 7; ks++) {
            int col = ks * 8 + (lane & 3);
            af[ks][0] = S[row * SS + col];
            af[ks][1] = S[(row + 8) * SS + col];
            af[ks][2] = S[row * SS + col + 4];
            af[ks][3] = S[(row + 8) * SS + col + 4];
        }
        float* outb = g_att + (size_t)w * N_TOK * C_DIM + h * HD;
        #pragma unroll
        for (int nt = 0; nt < 4; nt++) {
            float c[4] = {0.f, 0.f, 0.f, 0.f};
            #pragma unroll
            for (int ks = 0; ks < 7; ks++) {
                int kr = ks * 8 + (lane & 3);
                int nc = nt * 8 + (lane >> 2);
                uint32_t bf[2] = { Vs[kr * VS + nc], Vs[(kr + 4) * VS + nc] };
                mma_tf32(c, af[ks], bf);
            }
            const int i = warp * 16 + (lane >> 2);
            const int d = nt * 8 + 2 * (lane & 3);
            if (i < N_TOK)
                *(float2*)&outb[i * C_DIM + d] = make_float2(c[0], c[1]);
            if (i + 8 < N_TOK)
                *(float2*)&outb[(i + 8) * C_DIM + d] = make_float2(c[2], c[3]);
        }
    }
}

// ---------------- launch ----------------
extern "C" void kernel_launch(void* const* d_in, const int* in_sizes, int n_in,
                              void* d_out, int out_size)
{
    const float* x          = (const float*)d_in[0];
    const float* mask       = (const float*)d_in[1];
    const float* qkv_w      = (const float*)d_in[2];
    const float* qkv_b      = (const float*)d_in[3];
    const float* proj_w     = (const float*)d_in[4];
    const float* proj_b     = (const float*)d_in[5];
    const float* bias_table = (const float*)d_in[6];
    const int*   rel_index  = (const int*)d_in[7];
    float*       out        = (float*)d_out;

    void* qkv_ptr = nullptr;
    void* att_ptr = nullptr;
    cudaGetSymbolAddress(&qkv_ptr, g_qkv);
    cudaGetSymbolAddress(&att_ptr, g_att);

    const int gemm_smem = (2 * AS_WORDS + 2 * BS_WORDS) * 4;  // ~70KB
    static bool attr_set = false;
    if (!attr_set) {
        cudaFuncSetAttribute(gemm_tc_kernel<384>,
                             cudaFuncAttributeMaxDynamicSharedMemorySize, gemm_smem);
        cudaFuncSetAttribute(gemm_tc_kernel<128>,
                             cudaFuncAttributeMaxDynamicSharedMemorySize, gemm_smem);
        attr_set = true;
    }

    // bias+mask fusion table
    bm_kernel<<<(NWIN * N_TOK * N_TOK + 255) / 256, 256>>>(mask, bias_table, rel_index);

    // Stage A: qkv = x @ qkv_w + qkv_b
    gemm_tc_kernel<384><<<dim3(M_ROWS / 128, 384 / 128), 256, gemm_smem>>>(
        x, qkv_w, qkv_b, (float*)qkv_ptr);

    // Stage B: tensor-core windowed attention
    attn_tc_kernel<<<dim3(B_WIN, NH), 128>>>();

    // Stage C: out = att @ proj_w + proj_b
    gemm_tc_kernel<128><<<dim3(M_ROWS / 128, 128 / 128), 256, gemm_smem>>>(
        (const float*)att_ptr, proj_w, proj_b, out);
}